// round 2
// baseline (speedup 1.0000x reference)
#include <cuda_runtime.h>

#define IN_DIM  8192
#define OUT_DIM 8192
#define TPB     256
#define VPT     (IN_DIM / 4 / TPB)   // float4 loads per thread per row = 8
#define THRESH  50.0f

__global__ __launch_bounds__(TPB)
void snn_fused_kernel(const float* __restrict__ spike_input,
                      const float* __restrict__ states,
                      const float* __restrict__ v_mem,
                      const float* __restrict__ v_th,
                      const float* __restrict__ elig,
                      const float* __restrict__ noise,
                      float* __restrict__ out)
{
    __shared__ float s_warp[TPB / 32];
    __shared__ float s_spk;

    const int row = blockIdx.x;
    const int tid = threadIdx.x;

    const float4* sp4  = reinterpret_cast<const float4*>(spike_input);
    const float4* st4  = reinterpret_cast<const float4*>(states + (size_t)row * IN_DIM);
    const float4* el4  = reinterpret_cast<const float4*>(elig   + (size_t)row * IN_DIM);
    float4*       out4 = reinterpret_cast<float4*>(out + 3 * (size_t)OUT_DIM + (size_t)row * IN_DIM);

    // ---- phase 1: binary-weight GEMV dot product ----
    // states streamed (evict-first); spike_input stays cache-resident (32 KB).
    float acc = 0.0f;
    #pragma unroll
    for (int it = 0; it < VPT; ++it) {
        const int i = it * TPB + tid;
        float4 s  = __ldcs(&st4[i]);
        float4 sp = __ldg(&sp4[i]);
        if (s.x > THRESH) acc += sp.x;
        if (s.y > THRESH) acc += sp.y;
        if (s.z > THRESH) acc += sp.z;
        if (s.w > THRESH) acc += sp.w;
    }

    // ---- prefetch elig row BEFORE the reduction: overlap DRAM latency
    //      with the shuffle/barrier sequence (loads don't depend on spk) ----
    float4 e[VPT];
    #pragma unroll
    for (int it = 0; it < VPT; ++it)
        e[it] = __ldcs(&el4[it * TPB + tid]);

    // ---- block reduction of acc ----
    #pragma unroll
    for (int off = 16; off > 0; off >>= 1)
        acc += __shfl_xor_sync(0xFFFFFFFFu, acc, off);
    if ((tid & 31) == 0) s_warp[tid >> 5] = acc;
    __syncthreads();

    if (tid < 32) {
        float total = (tid < TPB / 32) ? s_warp[tid] : 0.0f;
        #pragma unroll
        for (int off = 4; off > 0; off >>= 1)
            total += __shfl_xor_sync(0xFFFFFFFFu, total, off);

        if (tid == 0) {
            const float vth   = v_th[row];
            const float v_new = v_mem[row] * 0.8f + total + noise[row];
            const float spk   = (v_new >= vth) ? 1.0f : 0.0f;

            // outputs: [spikes | v_mem_new | v_th_new | elig_new]
            out[row]           = spk;
            out[OUT_DIM + row] = v_new * (1.0f - spk) * 0.2f;
            float vth_new = vth + (spk - 0.05f) * 0.1f;
            out[2 * OUT_DIM + row] = fminf(fmaxf(vth_new, 0.5f), 10.0f);

            s_spk = spk;
        }
    }
    __syncthreads();

    // ---- phase 2: eligibility trace update (elig already in registers) ----
    const float spk = s_spk;
    #pragma unroll
    for (int it = 0; it < VPT; ++it) {
        const int i = it * TPB + tid;
        float4 sp = __ldg(&sp4[i]);           // L1 hit (same addr as phase 1)
        float4 r;
        r.x = fminf(fmaxf(fmaf(e[it].x, 0.95f, spk * sp.x), 0.0f), 5.0f);
        r.y = fminf(fmaxf(fmaf(e[it].y, 0.95f, spk * sp.y), 0.0f), 5.0f);
        r.z = fminf(fmaxf(fmaf(e[it].z, 0.95f, spk * sp.z), 0.0f), 5.0f);
        r.w = fminf(fmaxf(fmaf(e[it].w, 0.95f, spk * sp.w), 0.0f), 5.0f);
        __stcs(&out4[i], r);
    }
}

extern "C" void kernel_launch(void* const* d_in, const int* in_sizes, int n_in,
                              void* d_out, int out_size)
{
    const float* spike_input = (const float*)d_in[0];
    const float* states      = (const float*)d_in[1];
    const float* v_mem       = (const float*)d_in[2];
    const float* v_th        = (const float*)d_in[3];
    const float* elig        = (const float*)d_in[4];
    const float* noise       = (const float*)d_in[5];
    float* out = (float*)d_out;

    snn_fused_kernel<<<OUT_DIM, TPB>>>(spike_input, states, v_mem, v_th,
                                       elig, noise, out);
}